// round 1
// baseline (speedup 1.0000x reference)
#include <cuda_runtime.h>
#include <cuda_bf16.h>
#include <math.h>

// ---------------------------------------------------------------------------
// Problem constants
// ---------------------------------------------------------------------------
#define BATCH 256
#define GRID7 7
#define PBOX 2
#define NC 20
#define NBOX 98           // 7*7*2
#define KTOP 10
#define CONF_THR 0.1f
#define NMS_THR 0.7f
#define CELLF 64.0f
#define INPUTF 448.0f

#define CONV_CIN 1280
#define CONV_COUT 128
#define M_CONV (BATCH * 49)        // 12544
#define K_FC1 6272                 // 128*49
#define N_FC1 4096
#define N_FC2 1470

#define SPLIT1 4
#define SPLIT2 8

// ---------------------------------------------------------------------------
// Device scratch (static __device__ arrays: allocation-free)
// ---------------------------------------------------------------------------
__device__ float g_Xs[(size_t)M_CONV * CONV_CIN];           // 12544 x 1280 sliced input
__device__ float g_H1[(size_t)BATCH * K_FC1];               // conv output, fc1 input layout
__device__ float g_P1[(size_t)SPLIT1 * BATCH * N_FC1];      // fc1 split-K partials
__device__ float g_A2[(size_t)BATCH * N_FC1];               // fc1 activated
__device__ float g_P2[(size_t)SPLIT2 * BATCH * N_FC2];      // fc2 split-K partials
__device__ float g_F2[(size_t)BATCH * N_FC2];               // fc2 sigmoid output

// ---------------------------------------------------------------------------
// f32x2 packed FMA helpers (FFMA2 -- only reachable via PTX)
// ---------------------------------------------------------------------------
__device__ __forceinline__ unsigned long long pack2(float lo, float hi) {
    unsigned long long r;
    asm("mov.b64 %0, {%1, %2};" : "=l"(r) : "f"(lo), "f"(hi));
    return r;
}
__device__ __forceinline__ void unpack2(unsigned long long v, float& lo, float& hi) {
    asm("mov.b64 {%0, %1}, %2;" : "=f"(lo), "=f"(hi) : "l"(v));
}
__device__ __forceinline__ void ffma2(unsigned long long& d, unsigned long long a,
                                      unsigned long long b) {
    asm("fma.rn.f32x2 %0, %1, %2, %0;" : "+l"(d) : "l"(a), "l"(b));
}

// ---------------------------------------------------------------------------
// Kernel 1: strided slice + transpose  x[b,c,2i,2j] -> Xs[(b*49+p), c]
// block: (c-chunk of 32, batch)
// ---------------------------------------------------------------------------
__global__ void slice_kernel(const float* __restrict__ x) {
    __shared__ float sm[32 * 98];   // [cc][r(0..6)][j(0..13)]
    int b = blockIdx.y;
    int c0 = blockIdx.x * 32;
    const float* xb = x + (size_t)b * CONV_CIN * 196;
    for (int idx = threadIdx.x; idx < 32 * 98; idx += blockDim.x) {
        int cc = idx / 98, rem = idx % 98;
        int r = rem / 14, j = rem % 14;
        sm[idx] = xb[(size_t)(c0 + cc) * 196 + r * 28 + j];  // row 2r, col j
    }
    __syncthreads();
    for (int idx = threadIdx.x; idx < 49 * 32; idx += blockDim.x) {
        int p = idx / 32, cc = idx % 32;
        int i = p / 7, j = p % 7;
        g_Xs[((size_t)b * 49 + p) * CONV_CIN + c0 + cc] = sm[cc * 98 + i * 14 + 2 * j];
    }
}

// ---------------------------------------------------------------------------
// Tiled fp32 GEMM with packed f32x2 FMA.
// C[m,n] = sum_k A[m,k] * W[n,k]   (both K-contiguous row-major)
// CFG 0: conv  (A=g_Xs, out=g_H1 with transposed epilogue + bias)
// CFG 1: fc1   (A=g_H1, out=g_P1 split-K partial)
// CFG 2: fc2   (A=g_A2, out=g_P2 split-K partial)
// ---------------------------------------------------------------------------
template <int MT, int NT, int KT, int TM, int TN, int CFG>
__global__ __launch_bounds__((MT / TM) * (NT / TN))
void gemm_k(const float* __restrict__ W, const float* __restrict__ bias,
            int M, int N, int K, int klen) {
    constexpr int TX = NT / TN;
    constexpr int TY = MT / TM;
    constexpr int THREADS = TX * TY;
    constexpr int KV = KT / 4;                 // float4 chunks along k
    constexpr int AV = (MT * KV) / THREADS;    // float4 loads/thread for A tile
    constexpr int BV = (NT * KV) / THREADS;

    __shared__ float As[KT][MT + 4];
    __shared__ float Bs[KT][NT + 4];

    const float* A = (CFG == 0) ? g_Xs : (CFG == 1) ? g_H1 : g_A2;
    float* C = (CFG == 0) ? g_H1 : (CFG == 1) ? g_P1 : g_P2;
    if (CFG != 0) C += (size_t)blockIdx.z * M * N;

    int tid = threadIdx.x;
    int tx = tid % TX;
    int ty = tid / TX;
    int bm = blockIdx.x * MT;
    int bn = blockIdx.y * NT;
    int k0 = blockIdx.z * klen;

    unsigned long long acc[TM][TN / 2];
#pragma unroll
    for (int im = 0; im < TM; im++)
#pragma unroll
        for (int q = 0; q < TN / 2; q++) acc[im][q] = 0ull;

    const float* Ap = A + (size_t)bm * K + k0;
    const float* Wp = W + (size_t)bn * K + k0;

    for (int kk = 0; kk < klen; kk += KT) {
        // stage A tile (rows always in range: M is an exact multiple of MT)
#pragma unroll
        for (int v = 0; v < AV; v++) {
            int vid = tid + v * THREADS;
            int row = vid / KV, kq = vid % KV;
            float4 t = *reinterpret_cast<const float4*>(Ap + (size_t)row * K + kk + kq * 4);
            As[kq * 4 + 0][row] = t.x;
            As[kq * 4 + 1][row] = t.y;
            As[kq * 4 + 2][row] = t.z;
            As[kq * 4 + 3][row] = t.w;
        }
        // stage W tile (guard n for N=1470)
#pragma unroll
        for (int v = 0; v < BV; v++) {
            int vid = tid + v * THREADS;
            int row = vid / KV, kq = vid % KV;
            float4 t = make_float4(0.f, 0.f, 0.f, 0.f);
            if (bn + row < N)
                t = *reinterpret_cast<const float4*>(Wp + (size_t)row * K + kk + kq * 4);
            Bs[kq * 4 + 0][row] = t.x;
            Bs[kq * 4 + 1][row] = t.y;
            Bs[kq * 4 + 2][row] = t.z;
            Bs[kq * 4 + 3][row] = t.w;
        }
        __syncthreads();

#pragma unroll
        for (int k = 0; k < KT; k++) {
            float av[TM];
#pragma unroll
            for (int v = 0; v < TM / 4; v++) {
                float4 t = *reinterpret_cast<const float4*>(&As[k][ty * TM + 4 * v]);
                av[4 * v + 0] = t.x;
                av[4 * v + 1] = t.y;
                av[4 * v + 2] = t.z;
                av[4 * v + 3] = t.w;
            }
            unsigned long long bp[TN / 2];
#pragma unroll
            for (int q = 0; q < TN / 2; q++)
                bp[q] = *reinterpret_cast<const unsigned long long*>(&Bs[k][tx * TN + 2 * q]);
#pragma unroll
            for (int im = 0; im < TM; im++) {
                unsigned long long ap = pack2(av[im], av[im]);
#pragma unroll
                for (int q = 0; q < TN / 2; q++) ffma2(acc[im][q], ap, bp[q]);
            }
        }
        __syncthreads();
    }

    // epilogue
#pragma unroll
    for (int im = 0; im < TM; im++) {
        int m = bm + ty * TM + im;
#pragma unroll
        for (int q = 0; q < TN / 2; q++) {
            int n = bn + tx * TN + 2 * q;
            float lo, hi;
            unpack2(acc[im][q], lo, hi);
            if (CFG == 0) {
                // conv: m = b*49+p ; store H1[b*6272 + n*49 + p] (+bias)
                int bi = m / 49, p = m % 49;
                size_t base = (size_t)bi * K_FC1 + p;
                C[base + (size_t)n * 49] = lo + bias[n];
                C[base + (size_t)(n + 1) * 49] = hi + bias[n + 1];
            } else {
                if (n < N) C[(size_t)m * N + n] = lo;
                if (n + 1 < N) C[(size_t)m * N + n + 1] = hi;
            }
        }
    }
}

// ---------------------------------------------------------------------------
// Split-K reductions with bias + activation
// ---------------------------------------------------------------------------
__global__ void reduce_fc1(const float* __restrict__ bias) {
    int idx = blockIdx.x * blockDim.x + threadIdx.x;
    const int total = BATCH * N_FC1;
    if (idx < total) {
        int n = idx & (N_FC1 - 1);
        float s = bias[n];
#pragma unroll
        for (int sp = 0; sp < SPLIT1; sp++) s += g_P1[(size_t)sp * total + idx];
        g_A2[idx] = (s >= 0.f) ? s : 0.1f * s;
    }
}

__global__ void reduce_fc2(const float* __restrict__ bias) {
    int idx = blockIdx.x * blockDim.x + threadIdx.x;
    const int total = BATCH * N_FC2;
    if (idx < total) {
        int n = idx % N_FC2;
        float s = bias[n];
#pragma unroll
        for (int sp = 0; sp < SPLIT2; sp++) s += g_P2[(size_t)sp * total + idx];
        g_F2[idx] = 1.0f / (1.0f + expf(-s));
    }
}

// ---------------------------------------------------------------------------
// Decode + stable sort + NMS + top-k. One block per image.
// Output layout (fp32): boxes[256*10*4] | labels[256*10] | confs[256*10]
// ---------------------------------------------------------------------------
__global__ void nms_kernel(float* __restrict__ out) {
    __shared__ float conf_[NBOX];
    __shared__ float box_[NBOX][4];
    __shared__ int lab_[NBOX];
    __shared__ int order_[NBOX];
    __shared__ float sc_[NBOX];
    __shared__ float sbx_[NBOX][4];
    __shared__ int slb_[NBOX];
    __shared__ float iou_[NBOX * NBOX];
    __shared__ int keep_[NBOX];

    int b = blockIdx.x;
    int tid = threadIdx.x;
    const float* h = g_F2 + (size_t)b * N_FC2;

    // decode
    if (tid < NBOX) {
        int n = tid;
        int cell = n >> 1;
        int gi = cell / 7, gj = cell % 7;
        float sx = h[n * 4 + 0], sy = h[n * 4 + 1];
        float sw = h[n * 4 + 2], sh = h[n * 4 + 3];
        conf_[n] = h[NBOX * 4 + n];
        const float* cl = h + NBOX * 5 + cell * NC;
        float best = cl[0];
        int bi = 0;
#pragma unroll
        for (int c = 1; c < NC; c++)
            if (cl[c] > best) { best = cl[c]; bi = c; }
        lab_[n] = bi;
        float cx = sx * CELLF + (float)gi * CELLF;
        float cy = sy * CELLF + (float)gj * CELLF;
        float w = sw * INPUTF, hh = sh * INPUTF;
        float x1 = fminf(fmaxf(cx - 0.5f * w, 0.f), INPUTF);
        float y1 = fminf(fmaxf(cy - 0.5f * hh, 0.f), INPUTF);
        float x2 = fminf(fmaxf(cx + 0.5f * w, 0.f), INPUTF);
        float y2 = fminf(fmaxf(cy + 0.5f * hh, 0.f), INPUTF);
        box_[n][0] = x1; box_[n][1] = y1; box_[n][2] = x2; box_[n][3] = y2;
    }
    __syncthreads();

    // stable descending rank (matches jnp.argsort(-conf), stable)
    if (tid < NBOX) {
        float c = conf_[tid];
        int r = 0;
        for (int j = 0; j < NBOX; j++)
            r += (conf_[j] > c) || (conf_[j] == c && j < tid);
        order_[r] = tid;
    }
    __syncthreads();
    if (tid < NBOX) {
        int o = order_[tid];
        sc_[tid] = conf_[o];
        slb_[tid] = lab_[o];
        sbx_[tid][0] = box_[o][0]; sbx_[tid][1] = box_[o][1];
        sbx_[tid][2] = box_[o][2]; sbx_[tid][3] = box_[o][3];
    }
    __syncthreads();

    // pairwise IoU on sorted boxes
    for (int e = tid; e < NBOX * NBOX; e += blockDim.x) {
        int i = e / NBOX, j = e % NBOX;
        float ax1 = sbx_[i][0], ay1 = sbx_[i][1], ax2 = sbx_[i][2], ay2 = sbx_[i][3];
        float bx1 = sbx_[j][0], by1 = sbx_[j][1], bx2 = sbx_[j][2], by2 = sbx_[j][3];
        float areaA = fmaxf(ax2 - ax1, 0.f) * fmaxf(ay2 - ay1, 0.f);
        float areaB = fmaxf(bx2 - bx1, 0.f) * fmaxf(by2 - by1, 0.f);
        float ix1 = fmaxf(ax1, bx1), iy1 = fmaxf(ay1, by1);
        float ix2 = fminf(ax2, bx2), iy2 = fminf(ay2, by2);
        float inter = fmaxf(ix2 - ix1, 0.f) * fmaxf(iy2 - iy1, 0.f);
        float uni = areaA + areaB - inter;
        iou_[e] = (uni > 0.f) ? inter / uni : 0.f;
    }
    if (tid < NBOX) keep_[tid] = (sc_[tid] > CONF_THR) ? 1 : 0;
    __syncthreads();

    // greedy suppression (sequential over i, parallel over j)
    for (int i = 0; i < NBOX; i++) {
        if (keep_[i]) {
            for (int j = i + 1 + tid; j < NBOX; j += blockDim.x)
                if (iou_[i * NBOX + j] > NMS_THR) keep_[j] = 0;
        }
        __syncthreads();
    }

    // score + stable top-k (matches lax.top_k tie-break)
    if (tid < NBOX) conf_[tid] = keep_[tid] ? sc_[tid] : -1.0f;
    __syncthreads();
    if (tid < NBOX) {
        float s = conf_[tid];
        int r = 0;
        for (int j = 0; j < NBOX; j++)
            r += (conf_[j] > s) || (conf_[j] == s && j < tid);
        if (r < KTOP) {
            bool valid = s > CONF_THR;
            float* ob = out + ((size_t)b * KTOP + r) * 4;
            ob[0] = valid ? sbx_[tid][0] : 0.f;
            ob[1] = valid ? sbx_[tid][1] : 0.f;
            ob[2] = valid ? sbx_[tid][2] : 0.f;
            ob[3] = valid ? sbx_[tid][3] : 0.f;
            out[BATCH * KTOP * 4 + b * KTOP + r] = valid ? (float)slb_[tid] : 0.f;
            out[BATCH * KTOP * 5 + b * KTOP + r] = valid ? sc_[tid] : 0.f;
        }
    }
}

// ---------------------------------------------------------------------------
// Launch
// ---------------------------------------------------------------------------
extern "C" void kernel_launch(void* const* d_in, const int* in_sizes, int n_in,
                              void* d_out, int out_size) {
    const float* x = (const float*)d_in[0];
    const float* conv_w = (const float*)d_in[1];
    const float* conv_b = (const float*)d_in[2];
    const float* fc1_w = (const float*)d_in[3];
    const float* fc1_b = (const float*)d_in[4];
    const float* fc2_w = (const float*)d_in[5];
    const float* fc2_b = (const float*)d_in[6];
    float* out = (float*)d_out;

    // 1) strided slice + transpose
    slice_kernel<<<dim3(CONV_CIN / 32, BATCH), 256>>>(x);

    // 2) conv as GEMM: M=12544, N=128, K=1280  (64x128 tiles, 196 CTAs)
    gemm_k<64, 128, 16, 4, 8, 0><<<dim3(M_CONV / 64, 1, 1), 256>>>(
        conv_w, conv_b, M_CONV, CONV_COUT, CONV_CIN, CONV_CIN);

    // 3) fc1: M=256, N=4096, K=6272, split-K=4  (256 CTAs)
    gemm_k<128, 128, 16, 8, 8, 1><<<dim3(BATCH / 128, N_FC1 / 128, SPLIT1), 256>>>(
        fc1_w, nullptr, BATCH, N_FC1, K_FC1, K_FC1 / SPLIT1);
    reduce_fc1<<<(BATCH * N_FC1 + 255) / 256, 256>>>(fc1_b);

    // 4) fc2: M=256, N=1470, K=4096, split-K=8  (192 CTAs)
    gemm_k<128, 128, 16, 8, 8, 2><<<dim3(BATCH / 128, (N_FC2 + 127) / 128, SPLIT2), 256>>>(
        fc2_w, nullptr, BATCH, N_FC2, N_FC1, N_FC1 / SPLIT2);
    reduce_fc2<<<(BATCH * N_FC2 + 255) / 256, 256>>>(fc2_b);

    // 5) decode + NMS + top-k
    nms_kernel<<<BATCH, 128>>>(out);
}

// round 3
// speedup vs baseline: 1.4103x; 1.4103x over previous
#include <cuda_runtime.h>
#include <cuda_bf16.h>
#include <cstdint>
#include <math.h>

// ---------------------------------------------------------------------------
// Problem constants
// ---------------------------------------------------------------------------
#define BATCH 256
#define NC 20
#define NBOX 98
#define KTOP 10
#define CONF_THR 0.1f
#define NMS_THR 0.7f
#define CELLF 64.0f
#define INPUTF 448.0f

#define CONV_CIN 1280
#define CONV_COUT 128
#define M_CONV (BATCH * 49)        // 12544
#define K_FC1 6272
#define N_FC1 4096
#define N_FC2 1470

#define SPLIT1 2
#define SPLIT2 4

// ---------------------------------------------------------------------------
// Device scratch
// ---------------------------------------------------------------------------
__device__ float g_Xs[(size_t)M_CONV * CONV_CIN];
__device__ float g_H1[(size_t)BATCH * K_FC1];
__device__ float g_P1[(size_t)SPLIT1 * BATCH * N_FC1];
__device__ float g_A2[(size_t)BATCH * N_FC1];
__device__ float g_P2[(size_t)SPLIT2 * BATCH * N_FC2];
__device__ float g_F2[(size_t)BATCH * N_FC2];

// ---------------------------------------------------------------------------
// tf32 helpers
// ---------------------------------------------------------------------------
__device__ __forceinline__ float tf32r(float x) {
    uint32_t r;
    asm("cvt.rna.tf32.f32 %0, %1;" : "=r"(r) : "f"(x));
    return __uint_as_float(r);
}

__device__ __forceinline__ void mma_tf32(float* c, const uint32_t* a, const uint32_t* b) {
    asm volatile(
        "mma.sync.aligned.m16n8k8.row.col.f32.tf32.tf32.f32 "
        "{%0,%1,%2,%3}, {%4,%5,%6,%7}, {%8,%9}, {%0,%1,%2,%3};"
        : "+f"(c[0]), "+f"(c[1]), "+f"(c[2]), "+f"(c[3])
        : "r"(a[0]), "r"(a[1]), "r"(a[2]), "r"(a[3]), "r"(b[0]), "r"(b[1]));
}

// ---------------------------------------------------------------------------
// Kernel 1: strided slice + transpose  x[b,c,2i,2j] -> Xs[(b*49+p), c]
// ---------------------------------------------------------------------------
__global__ void slice_kernel(const float* __restrict__ x) {
    __shared__ float sm[32 * 98];
    int b = blockIdx.y;
    int c0 = blockIdx.x * 32;
    const float* xb = x + (size_t)b * CONV_CIN * 196;
    for (int idx = threadIdx.x; idx < 32 * 98; idx += blockDim.x) {
        int cc = idx / 98, rem = idx % 98;
        int r = rem / 14, j = rem % 14;
        sm[idx] = xb[(size_t)(c0 + cc) * 196 + r * 28 + j];
    }
    __syncthreads();
    for (int idx = threadIdx.x; idx < 49 * 32; idx += blockDim.x) {
        int p = idx / 32, cc = idx % 32;
        int i = p / 7, j = p % 7;
        g_Xs[((size_t)b * 49 + p) * CONV_CIN + c0 + cc] = sm[cc * 98 + i * 14 + 2 * j];
    }
}

// ---------------------------------------------------------------------------
// mma.sync tf32x3 GEMM.  C[m,n] = sum_k A[m,k]*W[n,k]
//   CFG 0: conv  A=g_Xs -> g_H1 (transposed layout + bias)
//   CFG 1: fc1   A=g_H1 -> g_P1[split]
//   CFG 2: fc2   A=g_A2 -> g_P2[split] (N=1470 guard)
// 128x128 CTA tile, 8 warps (2x4), warp tile 64x32, KT=16.
// Register-prefetch of chunk kt+1 overlaps LDG with mma of chunk kt.
// ---------------------------------------------------------------------------
#define KT 16
#define PITCH 20   // floats per smem row (bank-conflict-free fragment loads)

template <int CFG>
__global__ __launch_bounds__(256, 1)
void mma_gemm(const float* __restrict__ W, const float* __restrict__ bias,
              int K, int Ndim, int klen) {
    __shared__ float sAh[128 * PITCH];
    __shared__ float sAl[128 * PITCH];
    __shared__ float sBh[128 * PITCH];
    __shared__ float sBl[128 * PITCH];

    int tid = threadIdx.x;
    int warp = tid >> 5;
    int lane = tid & 31;
    int g = lane >> 2;
    int tg = lane & 3;
    int warpM = warp >> 2;          // 0..1
    int warpN = warp & 3;           // 0..3

    int bm = blockIdx.x * 128;
    int bn = blockIdx.y * 128;
    int k0g = blockIdx.z * klen;

    const float* A = (CFG == 0) ? g_Xs : (CFG == 1) ? g_H1 : g_A2;
    const float* Asrc = A + (size_t)bm * K + k0g;
    const float* Wsrc = W + (size_t)bn * K + k0g;

    // staging assignment: 2 float4 of A and 2 of B per thread per chunk
    int rowS[2], qS[2];
#pragma unroll
    for (int v = 0; v < 2; v++) {
        int vid = tid + v * 256;
        rowS[v] = vid >> 2;
        qS[v] = vid & 3;
    }
    bool bok[2];
#pragma unroll
    for (int v = 0; v < 2; v++) bok[v] = (CFG != 2) || (bn + rowS[v] < Ndim);

    float acc[4][4][4];
#pragma unroll
    for (int mt = 0; mt < 4; mt++)
#pragma unroll
        for (int nt = 0; nt < 4; nt++)
#pragma unroll
            for (int c = 0; c < 4; c++) acc[mt][nt][c] = 0.f;

    int nK = klen / KT;
    float4 nA[2], nB[2];

    // prefetch chunk 0
#pragma unroll
    for (int v = 0; v < 2; v++) {
        nA[v] = *reinterpret_cast<const float4*>(Asrc + (size_t)rowS[v] * K + qS[v] * 4);
        nB[v] = bok[v]
            ? *reinterpret_cast<const float4*>(Wsrc + (size_t)rowS[v] * K + qS[v] * 4)
            : make_float4(0.f, 0.f, 0.f, 0.f);
    }

    for (int kt = 0; kt < nK; kt++) {
        // split + store staged chunk into smem
#pragma unroll
        for (int v = 0; v < 2; v++) {
            float4 t = nA[v];
            float4 hi, lo;
            hi.x = tf32r(t.x); lo.x = tf32r(t.x - hi.x);
            hi.y = tf32r(t.y); lo.y = tf32r(t.y - hi.y);
            hi.z = tf32r(t.z); lo.z = tf32r(t.z - hi.z);
            hi.w = tf32r(t.w); lo.w = tf32r(t.w - hi.w);
            int off = rowS[v] * PITCH + qS[v] * 4;
            *reinterpret_cast<float4*>(&sAh[off]) = hi;
            *reinterpret_cast<float4*>(&sAl[off]) = lo;
            t = nB[v];
            hi.x = tf32r(t.x); lo.x = tf32r(t.x - hi.x);
            hi.y = tf32r(t.y); lo.y = tf32r(t.y - hi.y);
            hi.z = tf32r(t.z); lo.z = tf32r(t.z - hi.z);
            hi.w = tf32r(t.w); lo.w = tf32r(t.w - hi.w);
            *reinterpret_cast<float4*>(&sBh[off]) = hi;
            *reinterpret_cast<float4*>(&sBl[off]) = lo;
        }
        __syncthreads();

        // prefetch next chunk (LDG latency hides under mma below)
        if (kt + 1 < nK) {
            const float* Ap = Asrc + (kt + 1) * KT;
            const float* Wp = Wsrc + (kt + 1) * KT;
#pragma unroll
            for (int v = 0; v < 2; v++) {
                nA[v] = *reinterpret_cast<const float4*>(Ap + (size_t)rowS[v] * K + qS[v] * 4);
                nB[v] = bok[v]
                    ? *reinterpret_cast<const float4*>(Wp + (size_t)rowS[v] * K + qS[v] * 4)
                    : make_float4(0.f, 0.f, 0.f, 0.f);
            }
        }

        // compute: 2 k8 steps, 3 tf32 passes each
#pragma unroll
        for (int ks = 0; ks < 2; ks++) {
            int k0 = ks * 8;
            uint32_t ah[4][4], al[4][4], bh[4][2], bl[4][2];
#pragma unroll
            for (int mt = 0; mt < 4; mt++) {
                int base = (warpM * 64 + mt * 16 + g) * PITCH + k0;
                ah[mt][0] = __float_as_uint(sAh[base + tg]);
                ah[mt][1] = __float_as_uint(sAh[base + 8 * PITCH + tg]);
                ah[mt][2] = __float_as_uint(sAh[base + tg + 4]);
                ah[mt][3] = __float_as_uint(sAh[base + 8 * PITCH + tg + 4]);
                al[mt][0] = __float_as_uint(sAl[base + tg]);
                al[mt][1] = __float_as_uint(sAl[base + 8 * PITCH + tg]);
                al[mt][2] = __float_as_uint(sAl[base + tg + 4]);
                al[mt][3] = __float_as_uint(sAl[base + 8 * PITCH + tg + 4]);
            }
#pragma unroll
            for (int nt = 0; nt < 4; nt++) {
                int base = (warpN * 32 + nt * 8 + g) * PITCH + k0;
                bh[nt][0] = __float_as_uint(sBh[base + tg]);
                bh[nt][1] = __float_as_uint(sBh[base + tg + 4]);
                bl[nt][0] = __float_as_uint(sBl[base + tg]);
                bl[nt][1] = __float_as_uint(sBl[base + tg + 4]);
            }
#pragma unroll
            for (int mt = 0; mt < 4; mt++)
#pragma unroll
                for (int nt = 0; nt < 4; nt++) mma_tf32(acc[mt][nt], ah[mt], bh[nt]);
#pragma unroll
            for (int mt = 0; mt < 4; mt++)
#pragma unroll
                for (int nt = 0; nt < 4; nt++) mma_tf32(acc[mt][nt], ah[mt], bl[nt]);
#pragma unroll
            for (int mt = 0; mt < 4; mt++)
#pragma unroll
                for (int nt = 0; nt < 4; nt++) mma_tf32(acc[mt][nt], al[mt], bh[nt]);
        }
        __syncthreads();
    }

    // ---- epilogue ----
    if (CFG == 0) {
        // conv: D[m][n] -> g_H1[bi*6272 + n*49 + p] + bias[n]
#pragma unroll
        for (int mt = 0; mt < 4; mt++) {
#pragma unroll
            for (int nt = 0; nt < 4; nt++) {
                int n = warpN * 32 + nt * 8 + 2 * tg;
                float b0 = __ldg(&bias[n]), b1 = __ldg(&bias[n + 1]);
#pragma unroll
                for (int half = 0; half < 2; half++) {
                    int m = bm + warpM * 64 + mt * 16 + g + half * 8;
                    int bi = m / 49, p = m % 49;
                    float* dst = g_H1 + (size_t)bi * K_FC1 + p;
                    dst[(size_t)n * 49] = acc[mt][nt][half * 2 + 0] + b0;
                    dst[(size_t)(n + 1) * 49] = acc[mt][nt][half * 2 + 1] + b1;
                }
            }
        }
    } else {
        float* C = (CFG == 1) ? (g_P1 + (size_t)blockIdx.z * BATCH * N_FC1)
                              : (g_P2 + (size_t)blockIdx.z * BATCH * N_FC2);
#pragma unroll
        for (int mt = 0; mt < 4; mt++) {
#pragma unroll
            for (int nt = 0; nt < 4; nt++) {
                int n = bn + warpN * 32 + nt * 8 + 2 * tg;
                if (CFG == 2 && n >= Ndim) continue;
#pragma unroll
                for (int half = 0; half < 2; half++) {
                    int m = bm + warpM * 64 + mt * 16 + g + half * 8;
                    float2 v = make_float2(acc[mt][nt][half * 2 + 0], acc[mt][nt][half * 2 + 1]);
                    *reinterpret_cast<float2*>(C + (size_t)m * Ndim + n) = v;
                }
            }
        }
    }
}

// ---------------------------------------------------------------------------
// Split-K reductions with bias + activation
// ---------------------------------------------------------------------------
__global__ void reduce_fc1(const float* __restrict__ bias) {
    int idx = blockIdx.x * blockDim.x + threadIdx.x;
    const int total = BATCH * N_FC1;
    if (idx < total) {
        int n = idx & (N_FC1 - 1);
        float s = bias[n];
#pragma unroll
        for (int sp = 0; sp < SPLIT1; sp++) s += g_P1[(size_t)sp * total + idx];
        g_A2[idx] = (s >= 0.f) ? s : 0.1f * s;
    }
}

__global__ void reduce_fc2(const float* __restrict__ bias) {
    int idx = blockIdx.x * blockDim.x + threadIdx.x;
    const int total = BATCH * N_FC2;
    if (idx < total) {
        int n = idx % N_FC2;
        float s = bias[n];
#pragma unroll
        for (int sp = 0; sp < SPLIT2; sp++) s += g_P2[(size_t)sp * total + idx];
        g_F2[idx] = 1.0f / (1.0f + expf(-s));
    }
}

// ---------------------------------------------------------------------------
// Decode + stable sort + NMS + top-k. One block per image.
// ---------------------------------------------------------------------------
__global__ void nms_kernel(float* __restrict__ out) {
    __shared__ float conf_[NBOX];
    __shared__ float box_[NBOX][4];
    __shared__ int lab_[NBOX];
    __shared__ int order_[NBOX];
    __shared__ float sc_[NBOX];
    __shared__ float sbx_[NBOX][4];
    __shared__ int slb_[NBOX];
    __shared__ float iou_[NBOX * NBOX];
    __shared__ int keep_[NBOX];

    int b = blockIdx.x;
    int tid = threadIdx.x;
    const float* h = g_F2 + (size_t)b * N_FC2;

    if (tid < NBOX) {
        int n = tid;
        int cell = n >> 1;
        int gi = cell / 7, gj = cell % 7;
        float sx = h[n * 4 + 0], sy = h[n * 4 + 1];
        float sw = h[n * 4 + 2], sh = h[n * 4 + 3];
        conf_[n] = h[NBOX * 4 + n];
        const float* cl = h + NBOX * 5 + cell * NC;
        float best = cl[0];
        int bi = 0;
#pragma unroll
        for (int c = 1; c < NC; c++)
            if (cl[c] > best) { best = cl[c]; bi = c; }
        lab_[n] = bi;
        float cx = sx * CELLF + (float)gi * CELLF;
        float cy = sy * CELLF + (float)gj * CELLF;
        float w = sw * INPUTF, hh = sh * INPUTF;
        box_[n][0] = fminf(fmaxf(cx - 0.5f * w, 0.f), INPUTF);
        box_[n][1] = fminf(fmaxf(cy - 0.5f * hh, 0.f), INPUTF);
        box_[n][2] = fminf(fmaxf(cx + 0.5f * w, 0.f), INPUTF);
        box_[n][3] = fminf(fmaxf(cy + 0.5f * hh, 0.f), INPUTF);
    }
    __syncthreads();

    if (tid < NBOX) {
        float c = conf_[tid];
        int r = 0;
        for (int j = 0; j < NBOX; j++)
            r += (conf_[j] > c) || (conf_[j] == c && j < tid);
        order_[r] = tid;
    }
    __syncthreads();
    if (tid < NBOX) {
        int o = order_[tid];
        sc_[tid] = conf_[o];
        slb_[tid] = lab_[o];
        sbx_[tid][0] = box_[o][0]; sbx_[tid][1] = box_[o][1];
        sbx_[tid][2] = box_[o][2]; sbx_[tid][3] = box_[o][3];
    }
    __syncthreads();

    for (int e = tid; e < NBOX * NBOX; e += blockDim.x) {
        int i = e / NBOX, j = e % NBOX;
        float ax1 = sbx_[i][0], ay1 = sbx_[i][1], ax2 = sbx_[i][2], ay2 = sbx_[i][3];
        float bx1 = sbx_[j][0], by1 = sbx_[j][1], bx2 = sbx_[j][2], by2 = sbx_[j][3];
        float areaA = fmaxf(ax2 - ax1, 0.f) * fmaxf(ay2 - ay1, 0.f);
        float areaB = fmaxf(bx2 - bx1, 0.f) * fmaxf(by2 - by1, 0.f);
        float ix1 = fmaxf(ax1, bx1), iy1 = fmaxf(ay1, by1);
        float ix2 = fminf(ax2, bx2), iy2 = fminf(ay2, by2);
        float inter = fmaxf(ix2 - ix1, 0.f) * fmaxf(iy2 - iy1, 0.f);
        float uni = areaA + areaB - inter;
        iou_[e] = (uni > 0.f) ? inter / uni : 0.f;
    }
    if (tid < NBOX) keep_[tid] = (sc_[tid] > CONF_THR) ? 1 : 0;
    __syncthreads();

    for (int i = 0; i < NBOX; i++) {
        if (keep_[i]) {
            for (int j = i + 1 + tid; j < NBOX; j += blockDim.x)
                if (iou_[i * NBOX + j] > NMS_THR) keep_[j] = 0;
        }
        __syncthreads();
    }

    if (tid < NBOX) conf_[tid] = keep_[tid] ? sc_[tid] : -1.0f;
    __syncthreads();
    if (tid < NBOX) {
        float s = conf_[tid];
        int r = 0;
        for (int j = 0; j < NBOX; j++)
            r += (conf_[j] > s) || (conf_[j] == s && j < tid);
        if (r < KTOP) {
            bool valid = s > CONF_THR;
            float* ob = out + ((size_t)b * KTOP + r) * 4;
            ob[0] = valid ? sbx_[tid][0] : 0.f;
            ob[1] = valid ? sbx_[tid][1] : 0.f;
            ob[2] = valid ? sbx_[tid][2] : 0.f;
            ob[3] = valid ? sbx_[tid][3] : 0.f;
            out[BATCH * KTOP * 4 + b * KTOP + r] = valid ? (float)slb_[tid] : 0.f;
            out[BATCH * KTOP * 5 + b * KTOP + r] = valid ? sc_[tid] : 0.f;
        }
    }
}

// ---------------------------------------------------------------------------
// Launch
// ---------------------------------------------------------------------------
extern "C" void kernel_launch(void* const* d_in, const int* in_sizes, int n_in,
                              void* d_out, int out_size) {
    const float* x = (const float*)d_in[0];
    const float* conv_w = (const float*)d_in[1];
    const float* conv_b = (const float*)d_in[2];
    const float* fc1_w = (const float*)d_in[3];
    const float* fc1_b = (const float*)d_in[4];
    const float* fc2_w = (const float*)d_in[5];
    const float* fc2_b = (const float*)d_in[6];
    float* out = (float*)d_out;

    // 1) strided slice + transpose
    slice_kernel<<<dim3(CONV_CIN / 32, BATCH), 256>>>(x);

    // 2) conv GEMM: M=12544, N=128, K=1280 -> 98 CTAs
    mma_gemm<0><<<dim3(M_CONV / 128, 1, 1), 256>>>(conv_w, conv_b,
                                                   CONV_CIN, CONV_COUT, CONV_CIN);

    // 3) fc1: M=256, N=4096, K=6272, split-K=2 -> 128 CTAs
    mma_gemm<1><<<dim3(BATCH / 128, N_FC1 / 128, SPLIT1), 256>>>(fc1_w, nullptr,
                                                                 K_FC1, N_FC1, K_FC1 / SPLIT1);
    reduce_fc1<<<(BATCH * N_FC1 + 255) / 256, 256>>>(fc1_b);

    // 4) fc2: M=256, N=1470 (12 n-tiles), K=4096, split-K=4 -> 96 CTAs
    mma_gemm<2><<<dim3(BATCH / 128, 12, SPLIT2), 256>>>(fc2_w, nullptr,
                                                        N_FC1, N_FC2, N_FC1 / SPLIT2);
    reduce_fc2<<<(BATCH * N_FC2 + 255) / 256, 256>>>(fc2_b);

    // 5) decode + NMS + top-k
    nms_kernel<<<BATCH, 128>>>(out);
}